// round 7
// baseline (speedup 1.0000x reference)
#include <cuda_runtime.h>
#include <math.h>

typedef unsigned long long ull;

#define LAT 123
#define DIMA 128
#define HID 256
#define NT 50
#define NSTEP 49
#define NTHR 256
#define MROW 48
#define NBLK 128            // 6144/48, single wave

// smem layout (ull units): yin[48][128] dup | act[48][128] j2-packed | ksm 3*48*128 floats
#define ACT_OFF 6144
#define KSM_OFF 12288
#define SMEM_ULL (12288 + 9216)
#define SMEM_BYTES (SMEM_ULL*8)   // 172032 B

// packed weights (built once by pack_kernel)
__device__ ull g_w1jp[DIMA*128];   // [d][j2] = (W1[2j2][d], W1[2j2+1][d])
__device__ ull g_w2jp[128*DIMA];   // [j2][d] = (W2[d][2j2], W2[d][2j2+1])
__device__ ull g_b1p[128];         // (b1[2j2], b1[2j2+1])

__device__ __forceinline__ ull pk2(float lo, float hi){
  ull r; asm("mov.b64 %0, {%1, %2};" : "=l"(r) : "f"(lo), "f"(hi)); return r;
}
__device__ __forceinline__ void upk2(ull v, float &lo, float &hi){
  asm("mov.b64 {%0, %1}, %2;" : "=f"(lo), "=f"(hi) : "l"(v));
}
__device__ __forceinline__ ull fma2_(ull a, ull b, ull c){
  ull d; asm("fma.rn.f32x2 %0, %1, %2, %3;" : "=l"(d) : "l"(a), "l"(b), "l"(c)); return d;
}
__device__ __forceinline__ ull add2_(ull a, ull b){
  ull d; asm("add.rn.f32x2 %0, %1, %2;" : "=l"(d) : "l"(a), "l"(b)); return d;
}

__device__ __forceinline__ float fast_tanh(float x){
  float ax = fabsf(x);
  float e = __expf(-2.0f * ax);
  float r = __fdividef(1.0f - e, 1.0f + e);
  return copysignf(r, x);
}
__device__ __forceinline__ ull tanh2p(ull v){
  float lo, hi; upk2(v, lo, hi);
  return pk2(fast_tanh(lo), fast_tanh(hi));
}

__global__ void pack_kernel(const float* __restrict__ W1, const float* __restrict__ W2,
                            const float* __restrict__ b1){
  int i = blockIdx.x*256 + threadIdx.x;      // 0..16383
  int d  = i >> 7, j2 = i & 127;
  g_w1jp[i] = pk2(W1[(2*j2)*DIMA + d], W1[(2*j2+1)*DIMA + d]);
  int j2b = i >> 7, d2 = i & 127;
  g_w2jp[i] = pk2(W2[d2*HID + 2*j2b], W2[d2*HID + 2*j2b+1]);
  if (i < 128) g_b1p[i] = pk2(b1[2*i], b1[2*i+1]);
}

__global__ __launch_bounds__(NTHR,1)
void ode_kernel(const float* __restrict__ fp, const float* __restrict__ ts,
                const float* __restrict__ b2, float* __restrict__ out)
{
  extern __shared__ ull sm[];
  ull* yin = sm;                       // [r][d]  dup(y[r][d]), stride 128
  ull* act = sm + ACT_OFF;             // [r][j2] (tanh_{2j2}, tanh_{2j2+1}), stride 128
  float* ksm = (float*)(sm + KSM_OFF); // [s][r][d]

  const int tid = threadIdx.x;
  const int lg  = tid & 31;
  const int rg  = tid >> 5;
  const int r0  = rg*6;
  const int grow = blockIdx.x*MROW + r0;

  const int jA = 2*lg, jB = 64 + 2*lg;   // j2 pair-bases (thread owns j2 in {jA,jA+1,jB,jB+1})
  const int dA = 2*lg, dB = 64 + 2*lg;   // d bases for P2/RK4

  const ull b1A0 = g_b1p[jA], b1A1 = g_b1p[jA+1];
  const ull b1B0 = g_b1p[jB], b1B1 = g_b1p[jB+1];
  const float b2v[4] = { __ldg(b2+dA), __ldg(b2+dA+1), __ldg(b2+dB), __ldg(b2+dB+1) };

  // ---- init: y0 = [first_point | 0], write yin-dup + out[t=0] ----
  float y2[4][6];
  #pragma unroll
  for (int rr=0; rr<6; ++rr){
    int g = grow + rr;
    const float* fr = fp + (size_t)g*LAT;
    float v0 = (dA   < LAT) ? __ldg(fr+dA)   : 0.0f;
    float v1 = (dA+1 < LAT) ? __ldg(fr+dA+1) : 0.0f;
    float v2 = (dB   < LAT) ? __ldg(fr+dB)   : 0.0f;
    float v3 = (dB+1 < LAT) ? __ldg(fr+dB+1) : 0.0f;
    y2[0][rr]=v0; y2[1][rr]=v1; y2[2][rr]=v2; y2[3][rr]=v3;
    ulonglong2 s0; s0.x = pk2(v0,v0); s0.y = pk2(v1,v1);
    ulonglong2 s1; s1.x = pk2(v2,v2); s1.y = pk2(v3,v3);
    *(ulonglong2*)&yin[(r0+rr)*128 + dA] = s0;
    *(ulonglong2*)&yin[(r0+rr)*128 + dB] = s1;
    *(float2*)(out + ((size_t)g*NT)*DIMA + dA) = make_float2(v0,v1);
    *(float2*)(out + ((size_t)g*NT)*DIMA + dB) = make_float2(v2,v3);
  }
  __syncthreads();

  #pragma unroll 1
  for (int step=0; step<NSTEP; ++step){
    const float t0 = __ldg(ts+step);
    const float h  = __ldg(ts+step+1) - t0;

    #pragma unroll 1
    for (int st=0; st<4; ++st){
      // ========= P1: act[r][j2] = tanh(b1 + sum_d W1[j][d]*y[r][d]) (j-pair packed) =========
      ull acc[4][6];
      #pragma unroll
      for (int i=0;i<4;i++)
        #pragma unroll
        for (int rr=0;rr<6;rr++) acc[i][rr]=0ull;

      #pragma unroll 2
      for (int d=0; d<128; d+=2){
        const ull* w1b = g_w1jp + d*128;
        ulonglong2 wA = __ldg((const ulonglong2*)(w1b + jA));         // (j2=jA, jA+1) @ d
        ulonglong2 wB = __ldg((const ulonglong2*)(w1b + jB));
        ulonglong2 wC = __ldg((const ulonglong2*)(w1b + 128 + jA));   // @ d+1
        ulonglong2 wD = __ldg((const ulonglong2*)(w1b + 128 + jB));
        #pragma unroll
        for (int rr=0; rr<6; ++rr){
          ulonglong2 yv = *(const ulonglong2*)&yin[(r0+rr)*128 + d];  // dup y @ d, d+1 (broadcast)
          acc[0][rr]=fma2_(wA.x, yv.x, acc[0][rr]);
          acc[1][rr]=fma2_(wA.y, yv.x, acc[1][rr]);
          acc[2][rr]=fma2_(wB.x, yv.x, acc[2][rr]);
          acc[3][rr]=fma2_(wB.y, yv.x, acc[3][rr]);
          acc[0][rr]=fma2_(wC.x, yv.y, acc[0][rr]);
          acc[1][rr]=fma2_(wC.y, yv.y, acc[1][rr]);
          acc[2][rr]=fma2_(wD.x, yv.y, acc[2][rr]);
          acc[3][rr]=fma2_(wD.y, yv.y, acc[3][rr]);
        }
      }
      #pragma unroll
      for (int rr=0; rr<6; ++rr){
        ulonglong2 sA, sB;
        sA.x = tanh2p(add2_(acc[0][rr], b1A0));
        sA.y = tanh2p(add2_(acc[1][rr], b1A1));
        sB.x = tanh2p(add2_(acc[2][rr], b1B0));
        sB.y = tanh2p(add2_(acc[3][rr], b1B1));
        *(ulonglong2*)&act[(r0+rr)*128 + jA] = sA;
        *(ulonglong2*)&act[(r0+rr)*128 + jB] = sB;
      }
      __syncthreads();

      // ========= P2: k[r][d] = b2 + sum_j W2[d][j]*act[r][j]  (j-pair packed both ops) =========
      ull a2[4][6];
      #pragma unroll
      for (int i=0;i<4;i++)
        #pragma unroll
        for (int rr=0;rr<6;rr++) a2[i][rr]=0ull;

      #pragma unroll 2
      for (int j2=0; j2<128; j2+=2){
        const ull* w2b = g_w2jp + j2*128;
        ulonglong2 vA = __ldg((const ulonglong2*)(w2b + dA));         // (d=dA,dA+1) @ j2
        ulonglong2 vB = __ldg((const ulonglong2*)(w2b + dB));
        ulonglong2 vC = __ldg((const ulonglong2*)(w2b + 128 + dA));   // @ j2+1
        ulonglong2 vD = __ldg((const ulonglong2*)(w2b + 128 + dB));
        #pragma unroll
        for (int rr=0; rr<6; ++rr){
          ulonglong2 av = *(const ulonglong2*)&act[(r0+rr)*128 + j2]; // (j2, j2+1) (broadcast)
          a2[0][rr]=fma2_(vA.x, av.x, a2[0][rr]);
          a2[1][rr]=fma2_(vA.y, av.x, a2[1][rr]);
          a2[2][rr]=fma2_(vB.x, av.x, a2[2][rr]);
          a2[3][rr]=fma2_(vB.y, av.x, a2[3][rr]);
          a2[0][rr]=fma2_(vC.x, av.y, a2[0][rr]);
          a2[1][rr]=fma2_(vC.y, av.y, a2[1][rr]);
          a2[2][rr]=fma2_(vD.x, av.y, a2[2][rr]);
          a2[3][rr]=fma2_(vD.y, av.y, a2[3][rr]);
        }
      }
      // horizontal add + bias -> k
      float kk[4][6];
      #pragma unroll
      for (int i=0;i<4;i++)
        #pragma unroll
        for (int rr=0;rr<6;rr++){
          float lo, hi; upk2(a2[i][rr], lo, hi);
          kk[i][rr] = lo + hi + b2v[i];
        }

      // ========= RK4(3/8) stage update =========
      float* k0 = ksm;                 // [r][d]
      float* k1s = ksm + 6144;
      float* k2s = ksm + 12288;
      #pragma unroll
      for (int rr=0; rr<6; ++rr){
        const int ro = (r0+rr)*128;
        float yn[4];
        if (st == 0){
          *(float2*)&k0[ro+dA] = make_float2(kk[0][rr], kk[1][rr]);
          *(float2*)&k0[ro+dB] = make_float2(kk[2][rr], kk[3][rr]);
          const float c = h*(1.0f/3.0f);
          #pragma unroll
          for (int i=0;i<4;i++) yn[i] = fmaf(c, kk[i][rr], y2[i][rr]);
        } else if (st == 1){
          *(float2*)&k1s[ro+dA] = make_float2(kk[0][rr], kk[1][rr]);
          *(float2*)&k1s[ro+dB] = make_float2(kk[2][rr], kk[3][rr]);
          float2 p0 = *(float2*)&k0[ro+dA];
          float2 p1 = *(float2*)&k0[ro+dB];
          float k1v[4] = {p0.x, p0.y, p1.x, p1.y};
          const float c = -h*(1.0f/3.0f);
          #pragma unroll
          for (int i=0;i<4;i++) yn[i] = fmaf(c, k1v[i], fmaf(h, kk[i][rr], y2[i][rr]));
        } else if (st == 2){
          *(float2*)&k2s[ro+dA] = make_float2(kk[0][rr], kk[1][rr]);
          *(float2*)&k2s[ro+dB] = make_float2(kk[2][rr], kk[3][rr]);
          float2 p0 = *(float2*)&k0[ro+dA],  p1 = *(float2*)&k0[ro+dB];
          float2 q0 = *(float2*)&k1s[ro+dA], q1 = *(float2*)&k1s[ro+dB];
          float k1v[4] = {p0.x, p0.y, p1.x, p1.y};
          float k2v[4] = {q0.x, q0.y, q1.x, q1.y};
          #pragma unroll
          for (int i=0;i<4;i++) yn[i] = fmaf(h, k1v[i] - k2v[i] + kk[i][rr], y2[i][rr]);
        } else {
          float2 p0 = *(float2*)&k0[ro+dA],  p1 = *(float2*)&k0[ro+dB];
          float2 q0 = *(float2*)&k1s[ro+dA], q1 = *(float2*)&k1s[ro+dB];
          float2 s0 = *(float2*)&k2s[ro+dA], s1 = *(float2*)&k2s[ro+dB];
          float k1v[4] = {p0.x, p0.y, p1.x, p1.y};
          float k2v[4] = {q0.x, q0.y, q1.x, q1.y};
          float k3v[4] = {s0.x, s0.y, s1.x, s1.y};
          const float c = h*0.125f;
          #pragma unroll
          for (int i=0;i<4;i++){
            float sum = k1v[i] + kk[i][rr] + 3.0f*(k2v[i] + k3v[i]);
            yn[i] = fmaf(c, sum, y2[i][rr]);
            y2[i][rr] = yn[i];
          }
          int g = grow + rr;
          *(float2*)(out + ((size_t)g*NT + step+1)*DIMA + dA) = make_float2(yn[0], yn[1]);
          *(float2*)(out + ((size_t)g*NT + step+1)*DIMA + dB) = make_float2(yn[2], yn[3]);
        }
        ulonglong2 w0; w0.x = pk2(yn[0],yn[0]); w0.y = pk2(yn[1],yn[1]);
        ulonglong2 w1; w1.x = pk2(yn[2],yn[2]); w1.y = pk2(yn[3],yn[3]);
        *(ulonglong2*)&yin[ro + dA] = w0;
        *(ulonglong2*)&yin[ro + dB] = w1;
      }
      __syncthreads();
    }
  }
}

extern "C" void kernel_launch(void* const* d_in, const int* in_sizes, int n_in,
                              void* d_out, int out_size)
{
  const float* fp = (const float*)d_in[0];   // (3,2048,123)
  const float* ts = (const float*)d_in[1];   // (50)
  const float* W1 = (const float*)d_in[2];   // (256,128)
  const float* b1 = (const float*)d_in[3];   // (256)
  const float* W2 = (const float*)d_in[4];   // (128,256)
  const float* b2 = (const float*)d_in[5];   // (128)
  float* out = (float*)d_out;                // (3,2048,50,128)

  pack_kernel<<<64, 256>>>(W1, W2, b1);

  cudaFuncSetAttribute(ode_kernel,
                       cudaFuncAttributeMaxDynamicSharedMemorySize, SMEM_BYTES);
  ode_kernel<<<NBLK, NTHR, SMEM_BYTES>>>(fp, ts, b2, out);
}

// round 9
// speedup vs baseline: 1.2874x; 1.2874x over previous
#include <cuda_runtime.h>
#include <math.h>

typedef unsigned long long ull;

#define LAT 123
#define DIMA 128
#define HID 256
#define NT 50
#define NSTEP 49
#define NTHR 256
#define MROW 48
#define NBLK 128            // 6144/48, single wave

// smem layout (ull units): yin[48][128] dup | act[48][128] j2-packed | ksm 3*48*128 floats
#define ACT_OFF 6144
#define KSM_OFF 12288
#define SMEM_ULL (12288 + 9216)
#define SMEM_BYTES (SMEM_ULL*8)   // 172032 B

// packed weights (built once by pack_kernel); +8 rows pad so prefetch never reads OOB
__device__ ull g_w1jp[(DIMA+8)*128];   // [d][j2] = (W1[2j2][d], W1[2j2+1][d])
__device__ ull g_w2jp[(128+8)*DIMA];   // [j2][d] = (W2[d][2j2], W2[d][2j2+1])
__device__ ull g_b1p[128];             // (b1[2j2], b1[2j2+1])

__device__ __forceinline__ ull pk2(float lo, float hi){
  ull r; asm("mov.b64 %0, {%1, %2};" : "=l"(r) : "f"(lo), "f"(hi)); return r;
}
__device__ __forceinline__ void upk2(ull v, float &lo, float &hi){
  asm("mov.b64 {%0, %1}, %2;" : "=f"(lo), "=f"(hi) : "l"(v));
}
__device__ __forceinline__ ull fma2_(ull a, ull b, ull c){
  ull d; asm("fma.rn.f32x2 %0, %1, %2, %3;" : "=l"(d) : "l"(a), "l"(b), "l"(c)); return d;
}
__device__ __forceinline__ ull add2_(ull a, ull b){
  ull d; asm("add.rn.f32x2 %0, %1, %2;" : "=l"(d) : "l"(a), "l"(b)); return d;
}

__device__ __forceinline__ float fast_tanh(float x){
  float ax = fabsf(x);
  float e = __expf(-2.0f * ax);
  float r = __fdividef(1.0f - e, 1.0f + e);
  return copysignf(r, x);
}
__device__ __forceinline__ ull tanh2p(ull v){
  float lo, hi; upk2(v, lo, hi);
  return pk2(fast_tanh(lo), fast_tanh(hi));
}

__global__ void pack_kernel(const float* __restrict__ W1, const float* __restrict__ W2,
                            const float* __restrict__ b1){
  int i = blockIdx.x*256 + threadIdx.x;      // 0..16383
  int d  = i >> 7, j2 = i & 127;
  g_w1jp[i] = pk2(W1[(2*j2)*DIMA + d], W1[(2*j2+1)*DIMA + d]);
  int j2b = i >> 7, d2 = i & 127;
  g_w2jp[i] = pk2(W2[d2*HID + 2*j2b], W2[d2*HID + 2*j2b+1]);
  if (i < 128) g_b1p[i] = pk2(b1[2*i], b1[2*i+1]);
}

__global__ __launch_bounds__(NTHR,1)
void ode_kernel(const float* __restrict__ fp, const float* __restrict__ ts,
                const float* __restrict__ b2, float* __restrict__ out)
{
  extern __shared__ ull sm[];
  ull* yin = sm;                       // [r][d]  dup(y[r][d]), stride 128
  ull* act = sm + ACT_OFF;             // [r][j2] (tanh_{2j2}, tanh_{2j2+1}), stride 128
  float* ksm = (float*)(sm + KSM_OFF); // [s][r][d]

  const int tid = threadIdx.x;
  const int lg  = tid & 31;
  const int rg  = tid >> 5;            // warp id; warp owns rows r0..r0+5 end-to-end
  const int r0  = rg*6;
  const int grow = blockIdx.x*MROW + r0;

  const int jA = 2*lg, jB = 64 + 2*lg;   // j2 pair-bases
  const int dA = 2*lg, dB = 64 + 2*lg;   // d bases

  const ull b1A0 = g_b1p[jA], b1A1 = g_b1p[jA+1];
  const ull b1B0 = g_b1p[jB], b1B1 = g_b1p[jB+1];
  const float b2v[4] = { __ldg(b2+dA), __ldg(b2+dA+1), __ldg(b2+dB), __ldg(b2+dB+1) };

  // ---- init: y0 = [first_point | 0], write yin-dup + out[t=0] ----
  float y2[4][6];
  #pragma unroll
  for (int rr=0; rr<6; ++rr){
    int g = grow + rr;
    const float* fr = fp + (size_t)g*LAT;
    float v0 = (dA   < LAT) ? __ldg(fr+dA)   : 0.0f;
    float v1 = (dA+1 < LAT) ? __ldg(fr+dA+1) : 0.0f;
    float v2 = (dB   < LAT) ? __ldg(fr+dB)   : 0.0f;
    float v3 = (dB+1 < LAT) ? __ldg(fr+dB+1) : 0.0f;
    y2[0][rr]=v0; y2[1][rr]=v1; y2[2][rr]=v2; y2[3][rr]=v3;
    ulonglong2 s0; s0.x = pk2(v0,v0); s0.y = pk2(v1,v1);
    ulonglong2 s1; s1.x = pk2(v2,v2); s1.y = pk2(v3,v3);
    *(ulonglong2*)&yin[(r0+rr)*128 + dA] = s0;
    *(ulonglong2*)&yin[(r0+rr)*128 + dB] = s1;
    *(float2*)(out + ((size_t)g*NT)*DIMA + dA) = make_float2(v0,v1);
    *(float2*)(out + ((size_t)g*NT)*DIMA + dB) = make_float2(v2,v3);
  }
  __syncwarp();

  #pragma unroll 1
  for (int step=0; step<NSTEP; ++step){
    const float t0 = __ldg(ts+step);
    const float h  = __ldg(ts+step+1) - t0;

    #pragma unroll 1
    for (int st=0; st<4; ++st){
      // ========= P1: act[r][j2] = tanh(b1 + sum_d W1[j][d]*y[r][d]) =========
      // chunk c handles d=2c,2c+1; A/B double-buffer, prefetch distance 2
      ull acc[4][6];
      #pragma unroll
      for (int i=0;i<4;i++)
        #pragma unroll
        for (int rr=0;rr<6;rr++) acc[i][rr]=0ull;
      {
        ulonglong2 A0,A1,A2,A3, B0,B1,B2,B3;
        {
          const ull* b0 = g_w1jp;            // chunk 0
          A0=__ldg((const ulonglong2*)(b0+jA));     A1=__ldg((const ulonglong2*)(b0+jB));
          A2=__ldg((const ulonglong2*)(b0+128+jA)); A3=__ldg((const ulonglong2*)(b0+128+jB));
          const ull* b1b = g_w1jp + 256;     // chunk 1
          B0=__ldg((const ulonglong2*)(b1b+jA));     B1=__ldg((const ulonglong2*)(b1b+jB));
          B2=__ldg((const ulonglong2*)(b1b+128+jA)); B3=__ldg((const ulonglong2*)(b1b+128+jB));
        }
        #pragma unroll 1
        for (int cc=0; cc<64; cc+=2){
          {
            ulonglong2 c0=A0,c1=A1,c2=A2,c3=A3;
            const ull* nb = g_w1jp + (cc+2)*256;
            A0=__ldg((const ulonglong2*)(nb+jA));     A1=__ldg((const ulonglong2*)(nb+jB));
            A2=__ldg((const ulonglong2*)(nb+128+jA)); A3=__ldg((const ulonglong2*)(nb+128+jB));
            #pragma unroll
            for (int rr=0; rr<6; ++rr){
              ulonglong2 yv = *(const ulonglong2*)&yin[(r0+rr)*128 + 2*cc];
              acc[0][rr]=fma2_(c0.x, yv.x, acc[0][rr]);
              acc[1][rr]=fma2_(c0.y, yv.x, acc[1][rr]);
              acc[2][rr]=fma2_(c1.x, yv.x, acc[2][rr]);
              acc[3][rr]=fma2_(c1.y, yv.x, acc[3][rr]);
              acc[0][rr]=fma2_(c2.x, yv.y, acc[0][rr]);
              acc[1][rr]=fma2_(c2.y, yv.y, acc[1][rr]);
              acc[2][rr]=fma2_(c3.x, yv.y, acc[2][rr]);
              acc[3][rr]=fma2_(c3.y, yv.y, acc[3][rr]);
            }
          }
          {
            ulonglong2 c0=B0,c1=B1,c2=B2,c3=B3;
            const ull* nb = g_w1jp + (cc+3)*256;
            B0=__ldg((const ulonglong2*)(nb+jA));     B1=__ldg((const ulonglong2*)(nb+jB));
            B2=__ldg((const ulonglong2*)(nb+128+jA)); B3=__ldg((const ulonglong2*)(nb+128+jB));
            #pragma unroll
            for (int rr=0; rr<6; ++rr){
              ulonglong2 yv = *(const ulonglong2*)&yin[(r0+rr)*128 + 2*(cc+1)];
              acc[0][rr]=fma2_(c0.x, yv.x, acc[0][rr]);
              acc[1][rr]=fma2_(c0.y, yv.x, acc[1][rr]);
              acc[2][rr]=fma2_(c1.x, yv.x, acc[2][rr]);
              acc[3][rr]=fma2_(c1.y, yv.x, acc[3][rr]);
              acc[0][rr]=fma2_(c2.x, yv.y, acc[0][rr]);
              acc[1][rr]=fma2_(c2.y, yv.y, acc[1][rr]);
              acc[2][rr]=fma2_(c3.x, yv.y, acc[2][rr]);
              acc[3][rr]=fma2_(c3.y, yv.y, acc[3][rr]);
            }
          }
        }
      }
      #pragma unroll
      for (int rr=0; rr<6; ++rr){
        ulonglong2 sA, sB;
        sA.x = tanh2p(add2_(acc[0][rr], b1A0));
        sA.y = tanh2p(add2_(acc[1][rr], b1A1));
        sB.x = tanh2p(add2_(acc[2][rr], b1B0));
        sB.y = tanh2p(add2_(acc[3][rr], b1B1));
        *(ulonglong2*)&act[(r0+rr)*128 + jA] = sA;
        *(ulonglong2*)&act[(r0+rr)*128 + jB] = sB;
      }
      __syncwarp();   // warp-private rows: no block barrier needed

      // ========= P2: k[r][d] = b2 + sum_j W2[d][j]*act[r][j] =========
      ull a2[4][6];
      #pragma unroll
      for (int i=0;i<4;i++)
        #pragma unroll
        for (int rr=0;rr<6;rr++) a2[i][rr]=0ull;
      {
        ulonglong2 A0,A1,A2,A3, B0,B1,B2,B3;
        {
          const ull* b0 = g_w2jp;
          A0=__ldg((const ulonglong2*)(b0+dA));     A1=__ldg((const ulonglong2*)(b0+dB));
          A2=__ldg((const ulonglong2*)(b0+128+dA)); A3=__ldg((const ulonglong2*)(b0+128+dB));
          const ull* b1b = g_w2jp + 256;
          B0=__ldg((const ulonglong2*)(b1b+dA));     B1=__ldg((const ulonglong2*)(b1b+dB));
          B2=__ldg((const ulonglong2*)(b1b+128+dA)); B3=__ldg((const ulonglong2*)(b1b+128+dB));
        }
        #pragma unroll 1
        for (int cc=0; cc<64; cc+=2){
          {
            ulonglong2 c0=A0,c1=A1,c2=A2,c3=A3;
            const ull* nb = g_w2jp + (cc+2)*256;
            A0=__ldg((const ulonglong2*)(nb+dA));     A1=__ldg((const ulonglong2*)(nb+dB));
            A2=__ldg((const ulonglong2*)(nb+128+dA)); A3=__ldg((const ulonglong2*)(nb+128+dB));
            #pragma unroll
            for (int rr=0; rr<6; ++rr){
              ulonglong2 av = *(const ulonglong2*)&act[(r0+rr)*128 + 2*cc];
              a2[0][rr]=fma2_(c0.x, av.x, a2[0][rr]);
              a2[1][rr]=fma2_(c0.y, av.x, a2[1][rr]);
              a2[2][rr]=fma2_(c1.x, av.x, a2[2][rr]);
              a2[3][rr]=fma2_(c1.y, av.x, a2[3][rr]);
              a2[0][rr]=fma2_(c2.x, av.y, a2[0][rr]);
              a2[1][rr]=fma2_(c2.y, av.y, a2[1][rr]);
              a2[2][rr]=fma2_(c3.x, av.y, a2[2][rr]);
              a2[3][rr]=fma2_(c3.y, av.y, a2[3][rr]);
            }
          }
          {
            ulonglong2 c0=B0,c1=B1,c2=B2,c3=B3;
            const ull* nb = g_w2jp + (cc+3)*256;
            B0=__ldg((const ulonglong2*)(nb+dA));     B1=__ldg((const ulonglong2*)(nb+dB));
            B2=__ldg((const ulonglong2*)(nb+128+dA)); B3=__ldg((const ulonglong2*)(nb+128+dB));
            #pragma unroll
            for (int rr=0; rr<6; ++rr){
              ulonglong2 av = *(const ulonglong2*)&act[(r0+rr)*128 + 2*(cc+1)];
              a2[0][rr]=fma2_(c0.x, av.x, a2[0][rr]);
              a2[1][rr]=fma2_(c0.y, av.x, a2[1][rr]);
              a2[2][rr]=fma2_(c1.x, av.x, a2[2][rr]);
              a2[3][rr]=fma2_(c1.y, av.x, a2[3][rr]);
              a2[0][rr]=fma2_(c2.x, av.y, a2[0][rr]);
              a2[1][rr]=fma2_(c2.y, av.y, a2[1][rr]);
              a2[2][rr]=fma2_(c3.x, av.y, a2[2][rr]);
              a2[3][rr]=fma2_(c3.y, av.y, a2[3][rr]);
            }
          }
        }
      }
      // horizontal add + bias -> k
      float kk[4][6];
      #pragma unroll
      for (int i=0;i<4;i++)
        #pragma unroll
        for (int rr=0;rr<6;rr++){
          float lo, hi; upk2(a2[i][rr], lo, hi);
          kk[i][rr] = lo + hi + b2v[i];
        }

      // ========= RK4(3/8) stage update =========
      float* k0 = ksm;
      float* k1s = ksm + 6144;
      float* k2s = ksm + 12288;
      #pragma unroll
      for (int rr=0; rr<6; ++rr){
        const int ro = (r0+rr)*128;
        float yn[4];
        if (st == 0){
          *(float2*)&k0[ro+dA] = make_float2(kk[0][rr], kk[1][rr]);
          *(float2*)&k0[ro+dB] = make_float2(kk[2][rr], kk[3][rr]);
          const float c = h*(1.0f/3.0f);
          #pragma unroll
          for (int i=0;i<4;i++) yn[i] = fmaf(c, kk[i][rr], y2[i][rr]);
        } else if (st == 1){
          *(float2*)&k1s[ro+dA] = make_float2(kk[0][rr], kk[1][rr]);
          *(float2*)&k1s[ro+dB] = make_float2(kk[2][rr], kk[3][rr]);
          float2 p0 = *(float2*)&k0[ro+dA];
          float2 p1 = *(float2*)&k0[ro+dB];
          float k1v[4] = {p0.x, p0.y, p1.x, p1.y};
          const float c = -h*(1.0f/3.0f);
          #pragma unroll
          for (int i=0;i<4;i++) yn[i] = fmaf(c, k1v[i], fmaf(h, kk[i][rr], y2[i][rr]));
        } else if (st == 2){
          *(float2*)&k2s[ro+dA] = make_float2(kk[0][rr], kk[1][rr]);
          *(float2*)&k2s[ro+dB] = make_float2(kk[2][rr], kk[3][rr]);
          float2 p0 = *(float2*)&k0[ro+dA],  p1 = *(float2*)&k0[ro+dB];
          float2 q0 = *(float2*)&k1s[ro+dA], q1 = *(float2*)&k1s[ro+dB];
          float k1v[4] = {p0.x, p0.y, p1.x, p1.y};
          float k2v[4] = {q0.x, q0.y, q1.x, q1.y};
          #pragma unroll
          for (int i=0;i<4;i++) yn[i] = fmaf(h, k1v[i] - k2v[i] + kk[i][rr], y2[i][rr]);
        } else {
          float2 p0 = *(float2*)&k0[ro+dA],  p1 = *(float2*)&k0[ro+dB];
          float2 q0 = *(float2*)&k1s[ro+dA], q1 = *(float2*)&k1s[ro+dB];
          float2 s0 = *(float2*)&k2s[ro+dA], s1 = *(float2*)&k2s[ro+dB];
          float k1v[4] = {p0.x, p0.y, p1.x, p1.y};
          float k2v[4] = {q0.x, q0.y, q1.x, q1.y};
          float k3v[4] = {s0.x, s0.y, s1.x, s1.y};
          const float c = h*0.125f;
          #pragma unroll
          for (int i=0;i<4;i++){
            float sum = k1v[i] + kk[i][rr] + 3.0f*(k2v[i] + k3v[i]);
            yn[i] = fmaf(c, sum, y2[i][rr]);
            y2[i][rr] = yn[i];
          }
          int g = grow + rr;
          *(float2*)(out + ((size_t)g*NT + step+1)*DIMA + dA) = make_float2(yn[0], yn[1]);
          *(float2*)(out + ((size_t)g*NT + step+1)*DIMA + dB) = make_float2(yn[2], yn[3]);
        }
        ulonglong2 w0; w0.x = pk2(yn[0],yn[0]); w0.y = pk2(yn[1],yn[1]);
        ulonglong2 w1; w1.x = pk2(yn[2],yn[2]); w1.y = pk2(yn[3],yn[3]);
        *(ulonglong2*)&yin[ro + dA] = w0;
        *(ulonglong2*)&yin[ro + dB] = w1;
      }
      __syncwarp();   // warp-private rows: no block barrier needed
    }
  }
}

extern "C" void kernel_launch(void* const* d_in, const int* in_sizes, int n_in,
                              void* d_out, int out_size)
{
  const float* fp = (const float*)d_in[0];   // (3,2048,123)
  const float* ts = (const float*)d_in[1];   // (50)
  const float* W1 = (const float*)d_in[2];   // (256,128)
  const float* b1 = (const float*)d_in[3];   // (256)
  const float* W2 = (const float*)d_in[4];   // (128,256)
  const float* b2 = (const float*)d_in[5];   // (128)
  float* out = (float*)d_out;                // (3,2048,50,128)

  pack_kernel<<<64, 256>>>(W1, W2, b1);

  cudaFuncSetAttribute(ode_kernel,
                       cudaFuncAttributeMaxDynamicSharedMemorySize, SMEM_BYTES);
  ode_kernel<<<NBLK, NTHR, SMEM_BYTES>>>(fp, ts, b2, out);
}